// round 2
// baseline (speedup 1.0000x reference)
#include <cuda_runtime.h>
#include <math.h>

#define Nn 50000
#define Ee 1600000
#define INF_FEATS 64
#define Hh 128
#define Ll 5
#define Gg 512
#define Cc 10

// ---------------- scratch (device globals; no allocation allowed) ----------
__device__ float d_h[Nn * Hh];          // node state          25.6 MB
__device__ float d_m[Nn * Hh];          // h @ W_l             25.6 MB
__device__ float d_agg[Nn * Hh];        // scatter-add result  25.6 MB
__device__ float d_gi[Nn * 3 * Hh];     // agg @ w_ih^T        76.8 MB
__device__ float d_gh[Nn * 3 * Hh];     // h   @ w_hh^T        76.8 MB
__device__ float d_wihT[Hh * 3 * Hh];   // transposed weights
__device__ float d_whhT[Hh * 3 * Hh];
__device__ float d_pooled[Gg * Hh];
__device__ float d_hid[Gg * 4 * Hh];

// ---------------- helpers ---------------------------------------------------
__device__ __forceinline__ void red_add_f4(float* addr, float4 v) {
    asm volatile("red.global.add.v4.f32 [%0], {%1,%2,%3,%4};"
                 :: "l"(addr), "f"(v.x), "f"(v.y), "f"(v.z), "f"(v.w)
                 : "memory");
}

__device__ __forceinline__ float sigmoidf_(float x) {
    return 1.0f / (1.0f + expf(-x));
}

// ---------------- kernels ---------------------------------------------------

// h = pad(x, [N,64] -> [N,128])
__global__ void k_init_h(const float* __restrict__ x) {
    int i = blockIdx.x * blockDim.x + threadIdx.x;
    if (i >= Nn * Hh) return;
    int n = i >> 7, f = i & 127;
    d_h[i] = (f < INF_FEATS) ? x[n * INF_FEATS + f] : 0.0f;
}

// w_ihT[k][n] = w_ih[n][k], same for w_hh  (n in [0,384), k in [0,128))
__global__ void k_transpose_w(const float* __restrict__ wih,
                              const float* __restrict__ whh) {
    int i = blockIdx.x * blockDim.x + threadIdx.x;
    if (i >= 3 * Hh * Hh) return;
    int n = i / Hh, k = i % Hh;
    d_wihT[k * (3 * Hh) + n] = wih[i];
    d_whhT[k * (3 * Hh) + n] = whh[i];
}

__global__ void k_zero(float* __restrict__ p, int n) {
    int i = blockIdx.x * blockDim.x + threadIdx.x;
    if (i < n) p[i] = 0.0f;
}

// C[M,Nw] = A[M,128] @ B[128,Nw] (+ bias), tile 128x128, 256 thr, 8x8/thread
__global__ void k_gemm(const float* __restrict__ A, const float* __restrict__ B,
                       const float* __restrict__ bias, float* __restrict__ C,
                       int M, int Nw) {
    extern __shared__ float sm[];
    float* As = sm;              // [128][128]
    float* Bs = sm + 128 * 128;  // [128][128]

    int m0 = blockIdx.x * 128;
    int n0 = blockIdx.y * 128;
    int tid = threadIdx.x;

    // load A tile (rows m0..m0+127, all K=128), zero-fill OOB rows
    #pragma unroll
    for (int i = 0; i < 16; i++) {
        int e = tid + i * 256;          // 0..4095 float4 slots
        int r = e >> 5, c4 = e & 31;
        float4 v = make_float4(0.f, 0.f, 0.f, 0.f);
        if (m0 + r < M)
            v = reinterpret_cast<const float4*>(A + (size_t)(m0 + r) * 128)[c4];
        reinterpret_cast<float4*>(As + r * 128)[c4] = v;
    }
    // load B tile (all K rows, cols n0..n0+127)
    #pragma unroll
    for (int i = 0; i < 16; i++) {
        int e = tid + i * 256;
        int r = e >> 5, c4 = e & 31;
        float4 v = reinterpret_cast<const float4*>(B + (size_t)r * Nw + n0)[c4];
        reinterpret_cast<float4*>(Bs + r * 128)[c4] = v;
    }
    __syncthreads();

    int tx = tid & 15, ty = tid >> 4;   // 16x16 thread grid
    float acc[8][8];
    #pragma unroll
    for (int i = 0; i < 8; i++)
        #pragma unroll
        for (int j = 0; j < 8; j++) acc[i][j] = 0.0f;

    #pragma unroll 4
    for (int k = 0; k < 128; k++) {
        float b[8];
        *reinterpret_cast<float4*>(b)     = *reinterpret_cast<float4*>(Bs + k * 128 + tx * 8);
        *reinterpret_cast<float4*>(b + 4) = *reinterpret_cast<float4*>(Bs + k * 128 + tx * 8 + 4);
        float a[8];
        #pragma unroll
        for (int i = 0; i < 8; i++) a[i] = As[(ty * 8 + i) * 128 + k];
        #pragma unroll
        for (int i = 0; i < 8; i++)
            #pragma unroll
            for (int j = 0; j < 8; j++)
                acc[i][j] = fmaf(a[i], b[j], acc[i][j]);
    }

    #pragma unroll
    for (int i = 0; i < 8; i++) {
        int row = m0 + ty * 8 + i;
        if (row >= M) continue;
        float* crow = C + (size_t)row * Nw + n0 + tx * 8;
        #pragma unroll
        for (int j = 0; j < 8; j++) {
            float v = acc[i][j];
            if (bias) v += bias[n0 + tx * 8 + j];
            crow[j] = v;
        }
    }
}

// one warp per edge: agg[dst] += m[src] * ew   (float4 vector RED)
__global__ void k_edge(const int* __restrict__ ei, const float* __restrict__ ew) {
    int t = blockIdx.x * blockDim.x + threadIdx.x;
    int e = t >> 5;
    if (e >= Ee) return;
    int lane = t & 31;
    int s = ei[e];
    int d = ei[Ee + e];
    float w = ew[e];
    float4 v = reinterpret_cast<const float4*>(d_m)[(size_t)s * 32 + lane];
    v.x *= w; v.y *= w; v.z *= w; v.w *= w;
    red_add_f4(d_agg + (size_t)d * 128 + lane * 4, v);
}

// GRU cell elementwise: h = (1-z)*n + z*h
__global__ void k_gru() {
    int n = blockIdx.x;
    int f = threadIdx.x;
    const float* gi = d_gi + (size_t)n * 384;
    const float* gh = d_gh + (size_t)n * 384;
    float r  = sigmoidf_(gi[f] + gh[f]);
    float z  = sigmoidf_(gi[128 + f] + gh[128 + f]);
    float nn = tanhf(gi[256 + f] + r * gh[256 + f]);
    float ho = d_h[(size_t)n * 128 + f];
    d_h[(size_t)n * 128 + f] = (1.0f - z) * nn + z * ho;
}

__global__ void k_pool_init() {
    int i = blockIdx.x * blockDim.x + threadIdx.x;
    if (i < Gg * Hh) d_pooled[i] = -INFINITY;
}

// segment max via int/unsigned atomic trick (init -inf)
__global__ void k_pool(const int* __restrict__ batch) {
    int i = blockIdx.x * blockDim.x + threadIdx.x;
    if (i >= Nn * Hh) return;
    int n = i >> 7, f = i & 127;
    float v = d_h[i];
    int g = batch[n];
    float* addr = &d_pooled[g * Hh + f];
    if (v >= 0.0f)
        atomicMax(reinterpret_cast<int*>(addr), __float_as_int(v));
    else
        atomicMin(reinterpret_cast<unsigned*>(addr), __float_as_uint(v));
}

// hid[g] = relu(pooled[g] @ dense1_w^T + b1)   (block per graph)
__global__ void k_mlp1(const float* __restrict__ w, const float* __restrict__ b) {
    __shared__ float p[Hh];
    int g = blockIdx.x;
    p[threadIdx.x] = d_pooled[g * Hh + threadIdx.x];
    __syncthreads();
    for (int o = threadIdx.x; o < 4 * Hh; o += blockDim.x) {
        const float* wr = w + (size_t)o * Hh;
        float s = b[o];
        #pragma unroll 4
        for (int k = 0; k < Hh; k++) s = fmaf(p[k], wr[k], s);
        d_hid[g * 4 * Hh + o] = fmaxf(s, 0.0f);
    }
}

// out[g] = hid[g] @ dense2_w^T + b2   (block per graph, warp per class)
__global__ void k_mlp2(const float* __restrict__ w, const float* __restrict__ b,
                       float* __restrict__ out) {
    __shared__ float hsh[4 * Hh];
    int g = blockIdx.x;
    for (int i = threadIdx.x; i < 4 * Hh; i += blockDim.x)
        hsh[i] = d_hid[g * 4 * Hh + i];
    __syncthreads();
    int warp = threadIdx.x >> 5, lane = threadIdx.x & 31;
    if (warp < Cc) {
        const float* wr = w + (size_t)warp * (4 * Hh);
        float s = 0.0f;
        for (int k = lane; k < 4 * Hh; k += 32) s = fmaf(hsh[k], wr[k], s);
        #pragma unroll
        for (int off = 16; off; off >>= 1)
            s += __shfl_down_sync(0xffffffff, s, off);
        if (lane == 0) out[g * Cc + warp] = s + b[warp];
    }
}

// ---------------- launch ----------------------------------------------------
extern "C" void kernel_launch(void* const* d_in, const int* in_sizes, int n_in,
                              void* d_out, int out_size) {
    const float* x     = (const float*)d_in[0];
    const int*   ei    = (const int*)  d_in[1];
    const int*   batch = (const int*)  d_in[2];
    const float* ew    = (const float*)d_in[3];
    const float* weight= (const float*)d_in[4];
    const float* w_ih  = (const float*)d_in[5];
    const float* w_hh  = (const float*)d_in[6];
    const float* b_ih  = (const float*)d_in[7];
    const float* b_hh  = (const float*)d_in[8];
    const float* d1w   = (const float*)d_in[9];
    const float* d1b   = (const float*)d_in[10];
    const float* d2w   = (const float*)d_in[11];
    const float* d2b   = (const float*)d_in[12];
    float* out = (float*)d_out;

    float *ph, *pm, *pagg, *pgi, *pgh, *pwihT, *pwhhT;
    cudaGetSymbolAddress((void**)&ph,    d_h);
    cudaGetSymbolAddress((void**)&pm,    d_m);
    cudaGetSymbolAddress((void**)&pagg,  d_agg);
    cudaGetSymbolAddress((void**)&pgi,   d_gi);
    cudaGetSymbolAddress((void**)&pgh,   d_gh);
    cudaGetSymbolAddress((void**)&pwihT, d_wihT);
    cudaGetSymbolAddress((void**)&pwhhT, d_whhT);

    const int GEMM_SMEM = 2 * 128 * 128 * (int)sizeof(float);  // 128 KB
    cudaFuncSetAttribute(k_gemm, cudaFuncAttributeMaxDynamicSharedMemorySize,
                         GEMM_SMEM);

    const int NH = Nn * Hh;
    k_init_h<<<(NH + 255) / 256, 256>>>(x);
    k_transpose_w<<<(3 * Hh * Hh + 255) / 256, 256>>>(w_ih, w_hh);

    const int MB = (Nn + 127) / 128;  // 391 row tiles
    for (int l = 0; l < Ll; l++) {
        // m = h @ weight[l]
        k_gemm<<<dim3(MB, 1), 256, GEMM_SMEM>>>(ph, weight + (size_t)l * Hh * Hh,
                                                nullptr, pm, Nn, Hh);
        // agg = scatter_add(m[src] * ew, dst)
        k_zero<<<(NH + 255) / 256, 256>>>(pagg, NH);
        k_edge<<<(Ee * 32) / 256, 256>>>(ei, ew);
        // gi = agg @ w_ih^T + b_ih ; gh = h @ w_hh^T + b_hh
        k_gemm<<<dim3(MB, 3), 256, GEMM_SMEM>>>(pagg, pwihT, b_ih, pgi, Nn, 3 * Hh);
        k_gemm<<<dim3(MB, 3), 256, GEMM_SMEM>>>(ph,   pwhhT, b_hh, pgh, Nn, 3 * Hh);
        // h = GRU(agg-message, h)
        k_gru<<<Nn, Hh>>>();
    }

    k_pool_init<<<(Gg * Hh + 255) / 256, 256>>>();
    k_pool<<<(NH + 255) / 256, 256>>>(batch);
    k_mlp1<<<Gg, Hh>>>(d1w, d1b);
    k_mlp2<<<Gg, 320>>>(d2w, d2b, out);
}

// round 3
// speedup vs baseline: 1.5910x; 1.5910x over previous
#include <cuda_runtime.h>
#include <math.h>

#define Nn 50000
#define Ee 1600000
#define INF_FEATS 64
#define Hh 128
#define Ll 5
#define Gg 512
#define Cc 10

#define AS_STRIDE 132   // 128 + 4 pad  -> A-frag LDS conflict-free
#define BS_STRIDE 136   // 128 + 8 pad  -> B-frag LDS conflict-free

// ---------------- scratch (device globals; no allocation allowed) ----------
__device__ float d_h[Nn * Hh];
__device__ float d_m[Nn * Hh];
__device__ float d_agg[Nn * Hh];
__device__ float d_gi[Nn * 3 * Hh];
__device__ float d_gh[Nn * 3 * Hh];
__device__ float d_wihT[Hh * 3 * Hh];
__device__ float d_whhT[Hh * 3 * Hh];
__device__ float d_pooled[Gg * Hh];
__device__ float d_hid[Gg * 4 * Hh];

// ---------------- helpers ---------------------------------------------------
__device__ __forceinline__ void red_add_f4(float* addr, float4 v) {
    asm volatile("red.global.add.v4.f32 [%0], {%1,%2,%3,%4};"
                 :: "l"(addr), "f"(v.x), "f"(v.y), "f"(v.z), "f"(v.w)
                 : "memory");
}

__device__ __forceinline__ float sigmoidf_(float x) {
    return 1.0f / (1.0f + expf(-x));
}

__device__ __forceinline__ unsigned f2tf32(float f) {
    unsigned u;
    asm("cvt.rna.tf32.f32 %0, %1;" : "=r"(u) : "f"(f));
    return u;
}

__device__ __forceinline__ void mma_tf32(float c[4], const unsigned a[4],
                                         const unsigned b[2]) {
    asm volatile(
        "mma.sync.aligned.m16n8k8.row.col.f32.tf32.tf32.f32 "
        "{%0,%1,%2,%3}, {%4,%5,%6,%7}, {%8,%9}, {%0,%1,%2,%3};"
        : "+f"(c[0]), "+f"(c[1]), "+f"(c[2]), "+f"(c[3])
        : "r"(a[0]), "r"(a[1]), "r"(a[2]), "r"(a[3]), "r"(b[0]), "r"(b[1]));
}

// ---------------- kernels ---------------------------------------------------

__global__ void k_init_h(const float* __restrict__ x) {
    int i = blockIdx.x * blockDim.x + threadIdx.x;
    if (i >= Nn * Hh) return;
    int n = i >> 7, f = i & 127;
    d_h[i] = (f < INF_FEATS) ? x[n * INF_FEATS + f] : 0.0f;
}

__global__ void k_transpose_w(const float* __restrict__ wih,
                              const float* __restrict__ whh) {
    int i = blockIdx.x * blockDim.x + threadIdx.x;
    if (i >= 3 * Hh * Hh) return;
    int n = i / Hh, k = i % Hh;
    d_wihT[k * (3 * Hh) + n] = wih[i];
    d_whhT[k * (3 * Hh) + n] = whh[i];
}

__global__ void k_zero(float* __restrict__ p, int n) {
    int i = blockIdx.x * blockDim.x + threadIdx.x;
    if (i < n) p[i] = 0.0f;
}

// C[M,Nw] = A[M,128] @ B[128,Nw] (+bias), TF32 tensor cores.
// 128x128 block tile, 256 thr = 8 warps in 4x2 (m x n); warp tile 32x64.
__global__ void k_gemm_tc(const float* __restrict__ A, const float* __restrict__ B,
                          const float* __restrict__ bias, float* __restrict__ C,
                          int M, int Nw) {
    extern __shared__ float sm[];
    float* As = sm;                          // [128][AS_STRIDE]
    float* Bs = sm + 128 * AS_STRIDE;        // [128][BS_STRIDE]  (k rows, n cols)

    int m0 = blockIdx.x * 128;
    int n0 = blockIdx.y * 128;
    int tid = threadIdx.x;

    // A tile: rows m0..m0+127, K=128 cols. Convert to tf32 on the way in.
    #pragma unroll
    for (int i = 0; i < 16; i++) {
        int e = tid + i * 256;          // float4 slot 0..4095
        int r = e >> 5, c4 = e & 31;
        float4 v = make_float4(0.f, 0.f, 0.f, 0.f);
        if (m0 + r < M)
            v = reinterpret_cast<const float4*>(A + (size_t)(m0 + r) * 128)[c4];
        unsigned* dst = reinterpret_cast<unsigned*>(As + r * AS_STRIDE + c4 * 4);
        dst[0] = f2tf32(v.x); dst[1] = f2tf32(v.y);
        dst[2] = f2tf32(v.z); dst[3] = f2tf32(v.w);
    }
    // B tile: k rows 0..127, cols n0..n0+127
    #pragma unroll
    for (int i = 0; i < 16; i++) {
        int e = tid + i * 256;
        int r = e >> 5, c4 = e & 31;
        float4 v = reinterpret_cast<const float4*>(B + (size_t)r * Nw + n0)[c4];
        unsigned* dst = reinterpret_cast<unsigned*>(Bs + r * BS_STRIDE + c4 * 4);
        dst[0] = f2tf32(v.x); dst[1] = f2tf32(v.y);
        dst[2] = f2tf32(v.z); dst[3] = f2tf32(v.w);
    }
    __syncthreads();

    int wid = tid >> 5, lane = tid & 31;
    int wm = (wid & 3) * 32;        // warp m offset
    int wn = (wid >> 2) * 64;       // warp n offset
    int lr = lane >> 2;             // 0..7  (groupID)
    int lc = lane & 3;              // 0..3  (threadID_in_group)

    float acc[2][8][4];
    #pragma unroll
    for (int mt = 0; mt < 2; mt++)
        #pragma unroll
        for (int nt = 0; nt < 8; nt++)
            #pragma unroll
            for (int q = 0; q < 4; q++) acc[mt][nt][q] = 0.0f;

    const unsigned* Asu = reinterpret_cast<const unsigned*>(As);
    const unsigned* Bsu = reinterpret_cast<const unsigned*>(Bs);

    #pragma unroll
    for (int k0 = 0; k0 < 128; k0 += 8) {
        unsigned a[2][4], b[8][2];
        #pragma unroll
        for (int mt = 0; mt < 2; mt++) {
            const unsigned* ap = Asu + (wm + mt * 16 + lr) * AS_STRIDE + k0 + lc;
            a[mt][0] = ap[0];
            a[mt][1] = ap[8 * AS_STRIDE];
            a[mt][2] = ap[4];
            a[mt][3] = ap[8 * AS_STRIDE + 4];
        }
        #pragma unroll
        for (int nt = 0; nt < 8; nt++) {
            const unsigned* bp = Bsu + (k0 + lc) * BS_STRIDE + wn + nt * 8 + lr;
            b[nt][0] = bp[0];
            b[nt][1] = bp[4 * BS_STRIDE];
        }
        #pragma unroll
        for (int mt = 0; mt < 2; mt++)
            #pragma unroll
            for (int nt = 0; nt < 8; nt++)
                mma_tf32(acc[mt][nt], a[mt], b[nt]);
    }

    // epilogue: c0,c1 -> (row, col..col+1); c2,c3 -> (row+8, col..col+1)
    #pragma unroll
    for (int mt = 0; mt < 2; mt++) {
        #pragma unroll
        for (int nt = 0; nt < 8; nt++) {
            int row = m0 + wm + mt * 16 + lr;
            int col = n0 + wn + nt * 8 + lc * 2;
            float b0 = bias ? bias[col] : 0.0f;
            float b1 = bias ? bias[col + 1] : 0.0f;
            if (row < M) {
                float2 v = make_float2(acc[mt][nt][0] + b0, acc[mt][nt][1] + b1);
                *reinterpret_cast<float2*>(C + (size_t)row * Nw + col) = v;
            }
            if (row + 8 < M) {
                float2 v = make_float2(acc[mt][nt][2] + b0, acc[mt][nt][3] + b1);
                *reinterpret_cast<float2*>(C + (size_t)(row + 8) * Nw + col) = v;
            }
        }
    }
}

// one warp per edge: agg[dst] += m[src] * ew   (float4 vector RED)
__global__ void k_edge(const int* __restrict__ ei, const float* __restrict__ ew) {
    int t = blockIdx.x * blockDim.x + threadIdx.x;
    int e = t >> 5;
    if (e >= Ee) return;
    int lane = t & 31;
    int s = ei[e];
    int d = ei[Ee + e];
    float w = ew[e];
    float4 v = reinterpret_cast<const float4*>(d_m)[(size_t)s * 32 + lane];
    v.x *= w; v.y *= w; v.z *= w; v.w *= w;
    red_add_f4(d_agg + (size_t)d * 128 + lane * 4, v);
}

__global__ void k_gru() {
    int n = blockIdx.x;
    int f = threadIdx.x;
    const float* gi = d_gi + (size_t)n * 384;
    const float* gh = d_gh + (size_t)n * 384;
    float r  = sigmoidf_(gi[f] + gh[f]);
    float z  = sigmoidf_(gi[128 + f] + gh[128 + f]);
    float nn = tanhf(gi[256 + f] + r * gh[256 + f]);
    float ho = d_h[(size_t)n * 128 + f];
    d_h[(size_t)n * 128 + f] = (1.0f - z) * nn + z * ho;
}

__global__ void k_pool_init() {
    int i = blockIdx.x * blockDim.x + threadIdx.x;
    if (i < Gg * Hh) d_pooled[i] = -INFINITY;
}

__global__ void k_pool(const int* __restrict__ batch) {
    int i = blockIdx.x * blockDim.x + threadIdx.x;
    if (i >= Nn * Hh) return;
    int n = i >> 7, f = i & 127;
    float v = d_h[i];
    int g = batch[n];
    float* addr = &d_pooled[g * Hh + f];
    if (v >= 0.0f)
        atomicMax(reinterpret_cast<int*>(addr), __float_as_int(v));
    else
        atomicMin(reinterpret_cast<unsigned*>(addr), __float_as_uint(v));
}

__global__ void k_mlp1(const float* __restrict__ w, const float* __restrict__ b) {
    __shared__ float p[Hh];
    int g = blockIdx.x;
    p[threadIdx.x] = d_pooled[g * Hh + threadIdx.x];
    __syncthreads();
    for (int o = threadIdx.x; o < 4 * Hh; o += blockDim.x) {
        const float* wr = w + (size_t)o * Hh;
        float s = b[o];
        #pragma unroll 4
        for (int k = 0; k < Hh; k++) s = fmaf(p[k], wr[k], s);
        d_hid[g * 4 * Hh + o] = fmaxf(s, 0.0f);
    }
}

__global__ void k_mlp2(const float* __restrict__ w, const float* __restrict__ b,
                       float* __restrict__ out) {
    __shared__ float hsh[4 * Hh];
    int g = blockIdx.x;
    for (int i = threadIdx.x; i < 4 * Hh; i += blockDim.x)
        hsh[i] = d_hid[g * 4 * Hh + i];
    __syncthreads();
    int warp = threadIdx.x >> 5, lane = threadIdx.x & 31;
    if (warp < Cc) {
        const float* wr = w + (size_t)warp * (4 * Hh);
        float s = 0.0f;
        for (int k = lane; k < 4 * Hh; k += 32) s = fmaf(hsh[k], wr[k], s);
        #pragma unroll
        for (int off = 16; off; off >>= 1)
            s += __shfl_down_sync(0xffffffff, s, off);
        if (lane == 0) out[g * Cc + warp] = s + b[warp];
    }
}

// ---------------- launch ----------------------------------------------------
extern "C" void kernel_launch(void* const* d_in, const int* in_sizes, int n_in,
                              void* d_out, int out_size) {
    const float* x     = (const float*)d_in[0];
    const int*   ei    = (const int*)  d_in[1];
    const int*   batch = (const int*)  d_in[2];
    const float* ew    = (const float*)d_in[3];
    const float* weight= (const float*)d_in[4];
    const float* w_ih  = (const float*)d_in[5];
    const float* w_hh  = (const float*)d_in[6];
    const float* b_ih  = (const float*)d_in[7];
    const float* b_hh  = (const float*)d_in[8];
    const float* d1w   = (const float*)d_in[9];
    const float* d1b   = (const float*)d_in[10];
    const float* d2w   = (const float*)d_in[11];
    const float* d2b   = (const float*)d_in[12];
    float* out = (float*)d_out;

    float *ph, *pm, *pagg, *pgi, *pgh, *pwihT, *pwhhT;
    cudaGetSymbolAddress((void**)&ph,    d_h);
    cudaGetSymbolAddress((void**)&pm,    d_m);
    cudaGetSymbolAddress((void**)&pagg,  d_agg);
    cudaGetSymbolAddress((void**)&pgi,   d_gi);
    cudaGetSymbolAddress((void**)&pgh,   d_gh);
    cudaGetSymbolAddress((void**)&pwihT, d_wihT);
    cudaGetSymbolAddress((void**)&pwhhT, d_whhT);

    const int GEMM_SMEM = (128 * AS_STRIDE + 128 * BS_STRIDE) * (int)sizeof(float);
    cudaFuncSetAttribute(k_gemm_tc, cudaFuncAttributeMaxDynamicSharedMemorySize,
                         GEMM_SMEM);

    const int NH = Nn * Hh;
    k_init_h<<<(NH + 255) / 256, 256>>>(x);
    k_transpose_w<<<(3 * Hh * Hh + 255) / 256, 256>>>(w_ih, w_hh);

    const int MB = (Nn + 127) / 128;  // 391 row tiles
    for (int l = 0; l < Ll; l++) {
        // m = h @ weight[l]
        k_gemm_tc<<<dim3(MB, 1), 256, GEMM_SMEM>>>(
            ph, weight + (size_t)l * Hh * Hh, nullptr, pm, Nn, Hh);
        // agg = scatter_add(m[src] * ew, dst)
        k_zero<<<(NH + 255) / 256, 256>>>(pagg, NH);
        k_edge<<<(Ee * 32) / 256, 256>>>(ei, ew);
        // gi = agg @ w_ih^T + b_ih ; gh = h @ w_hh^T + b_hh
        k_gemm_tc<<<dim3(MB, 3), 256, GEMM_SMEM>>>(pagg, pwihT, b_ih, pgi, Nn, 3 * Hh);
        k_gemm_tc<<<dim3(MB, 3), 256, GEMM_SMEM>>>(ph,   pwhhT, b_hh, pgh, Nn, 3 * Hh);
        // h = GRU(agg-message, h)
        k_gru<<<Nn, Hh>>>();
    }

    k_pool_init<<<(Gg * Hh + 255) / 256, 256>>>();
    k_pool<<<(NH + 255) / 256, 256>>>(batch);
    k_mlp1<<<Gg, Hh>>>(d1w, d1b);
    k_mlp2<<<Gg, 320>>>(d2w, d2b, out);
}

// round 4
// speedup vs baseline: 2.2147x; 1.3921x over previous
#include <cuda_runtime.h>
#include <math.h>

#define Nn 50000
#define Ee 1600000
#define INF_FEATS 64
#define Hh 128
#define Ll 5
#define Gg 512
#define Cc 10

#define AS_STRIDE 132   // 128 + 4 pad  -> A-frag LDS conflict-free
#define BS_STRIDE 136   // 128 + 8 pad  -> B-frag LDS conflict-free

// ---------------- scratch (device globals; no allocation allowed) ----------
__device__ float d_h[Nn * Hh];            // node state
__device__ float d_mgh[Nn * 512];         // [m (128) | gh (384)] fused GEMM out
__device__ float d_agg[Nn * Hh];          // gathered messages
__device__ float d_gi[Nn * 3 * Hh];       // agg @ w_ih^T
__device__ float d_wihT[Hh * 3 * Hh];     // w_ih transposed [128,384]
__device__ float d_Bcat[Ll * Hh * 512];   // per-layer [W_l | w_hh^T]  [128,512]
__device__ float d_bcat[512];             // [0 | b_hh]
__device__ float d_pooled[Gg * Hh];
__device__ float d_hid[Gg * 4 * Hh];
// CSR scratch
__device__ int   d_deg[Nn];
__device__ int   d_rowstart[Nn + 1];
__device__ int   d_cursor[Nn];
__device__ int   d_esrc[Ee];
__device__ float d_ews[Ee];

// ---------------- helpers ---------------------------------------------------
__device__ __forceinline__ float sigmoidf_(float x) {
    return 1.0f / (1.0f + expf(-x));
}

__device__ __forceinline__ unsigned f2tf32(float f) {
    unsigned u;
    asm("cvt.rna.tf32.f32 %0, %1;" : "=r"(u) : "f"(f));
    return u;
}

__device__ __forceinline__ void mma_tf32(float c[4], const unsigned a[4],
                                         const unsigned b[2]) {
    asm volatile(
        "mma.sync.aligned.m16n8k8.row.col.f32.tf32.tf32.f32 "
        "{%0,%1,%2,%3}, {%4,%5,%6,%7}, {%8,%9}, {%0,%1,%2,%3};"
        : "+f"(c[0]), "+f"(c[1]), "+f"(c[2]), "+f"(c[3])
        : "r"(a[0]), "r"(a[1]), "r"(a[2]), "r"(a[3]), "r"(b[0]), "r"(b[1]));
}

// ---------------- setup kernels ---------------------------------------------

__global__ void k_init_h(const float* __restrict__ x) {
    int i = blockIdx.x * blockDim.x + threadIdx.x;
    if (i >= Nn * Hh) return;
    int n = i >> 7, f = i & 127;
    d_h[i] = (f < INF_FEATS) ? x[n * INF_FEATS + f] : 0.0f;
}

// wihT[k][n] = w_ih[n][k]
__global__ void k_transpose_wih(const float* __restrict__ wih) {
    int i = blockIdx.x * blockDim.x + threadIdx.x;
    if (i >= 3 * Hh * Hh) return;
    int n = i / Hh, k = i % Hh;
    d_wihT[k * (3 * Hh) + n] = wih[i];
}

// Bcat[l][k][c] = (c<128) ? weight[l][k][c] : w_hh[c-128][k];  bcat too
__global__ void k_build_bcat(const float* __restrict__ weight,
                             const float* __restrict__ whh,
                             const float* __restrict__ bhh) {
    int i = blockIdx.x * blockDim.x + threadIdx.x;
    if (i < 512) d_bcat[i] = (i < 128) ? 0.0f : bhh[i - 128];
    if (i >= Ll * Hh * 512) return;
    int l = i / (Hh * 512);
    int r = i % (Hh * 512);
    int k = r / 512, c = r % 512;
    d_Bcat[i] = (c < 128) ? weight[(size_t)l * Hh * Hh + k * Hh + c]
                          : whh[(size_t)(c - 128) * Hh + k];
}

// ---------------- CSR build --------------------------------------------------
__global__ void k_deg_zero() {
    int i = blockIdx.x * blockDim.x + threadIdx.x;
    if (i < Nn) d_deg[i] = 0;
}

__global__ void k_hist(const int* __restrict__ ei) {
    int e = blockIdx.x * blockDim.x + threadIdx.x;
    if (e < Ee) atomicAdd(&d_deg[ei[Ee + e]], 1);
}

// single-block exclusive scan over d_deg -> d_rowstart / d_cursor
__global__ void k_scan() {
    __shared__ int sp[1024];
    const int CH = (Nn + 1023) / 1024;   // 49
    int t = threadIdx.x;
    int base = t * CH;
    int s = 0;
    for (int i = 0; i < CH; i++) {
        int idx = base + i;
        if (idx < Nn) s += d_deg[idx];
    }
    sp[t] = s;
    __syncthreads();
    // Hillis-Steele inclusive scan
    for (int d = 1; d < 1024; d <<= 1) {
        int add = (t >= d) ? sp[t - d] : 0;
        __syncthreads();
        sp[t] += add;
        __syncthreads();
    }
    int off = sp[t] - s;   // exclusive prefix for this chunk
    for (int i = 0; i < CH; i++) {
        int idx = base + i;
        if (idx < Nn) {
            d_rowstart[idx] = off;
            d_cursor[idx] = off;
            off += d_deg[idx];
        }
    }
    if (t == 1023) d_rowstart[Nn] = off;
}

__global__ void k_scatter(const int* __restrict__ ei, const float* __restrict__ ew) {
    int e = blockIdx.x * blockDim.x + threadIdx.x;
    if (e >= Ee) return;
    int dst = ei[Ee + e];
    int pos = atomicAdd(&d_cursor[dst], 1);
    d_esrc[pos] = ei[e];
    d_ews[pos] = ew[e];
}

// ---------------- GEMM (tf32 tensor cores) -----------------------------------
// C[M,Nw] = A[M,128] @ B[128,Nw] (+bias). 128x128 tile, 256 thr, warp 32x64.
__global__ void k_gemm_tc(const float* __restrict__ A, const float* __restrict__ B,
                          const float* __restrict__ bias, float* __restrict__ C,
                          int M, int Nw) {
    extern __shared__ float sm[];
    float* As = sm;                          // [128][AS_STRIDE]
    float* Bs = sm + 128 * AS_STRIDE;        // [128][BS_STRIDE]

    int m0 = blockIdx.x * 128;
    int n0 = blockIdx.y * 128;
    int tid = threadIdx.x;

    #pragma unroll
    for (int i = 0; i < 16; i++) {
        int e = tid + i * 256;
        int r = e >> 5, c4 = e & 31;
        float4 v = make_float4(0.f, 0.f, 0.f, 0.f);
        if (m0 + r < M)
            v = reinterpret_cast<const float4*>(A + (size_t)(m0 + r) * 128)[c4];
        unsigned* dst = reinterpret_cast<unsigned*>(As + r * AS_STRIDE + c4 * 4);
        dst[0] = f2tf32(v.x); dst[1] = f2tf32(v.y);
        dst[2] = f2tf32(v.z); dst[3] = f2tf32(v.w);
    }
    #pragma unroll
    for (int i = 0; i < 16; i++) {
        int e = tid + i * 256;
        int r = e >> 5, c4 = e & 31;
        float4 v = reinterpret_cast<const float4*>(B + (size_t)r * Nw + n0)[c4];
        unsigned* dst = reinterpret_cast<unsigned*>(Bs + r * BS_STRIDE + c4 * 4);
        dst[0] = f2tf32(v.x); dst[1] = f2tf32(v.y);
        dst[2] = f2tf32(v.z); dst[3] = f2tf32(v.w);
    }
    __syncthreads();

    int wid = tid >> 5, lane = tid & 31;
    int wm = (wid & 3) * 32;
    int wn = (wid >> 2) * 64;
    int lr = lane >> 2;
    int lc = lane & 3;

    float acc[2][8][4];
    #pragma unroll
    for (int mt = 0; mt < 2; mt++)
        #pragma unroll
        for (int nt = 0; nt < 8; nt++)
            #pragma unroll
            for (int q = 0; q < 4; q++) acc[mt][nt][q] = 0.0f;

    const unsigned* Asu = reinterpret_cast<const unsigned*>(As);
    const unsigned* Bsu = reinterpret_cast<const unsigned*>(Bs);

    #pragma unroll
    for (int k0 = 0; k0 < 128; k0 += 8) {
        unsigned a[2][4], b[8][2];
        #pragma unroll
        for (int mt = 0; mt < 2; mt++) {
            const unsigned* ap = Asu + (wm + mt * 16 + lr) * AS_STRIDE + k0 + lc;
            a[mt][0] = ap[0];
            a[mt][1] = ap[8 * AS_STRIDE];
            a[mt][2] = ap[4];
            a[mt][3] = ap[8 * AS_STRIDE + 4];
        }
        #pragma unroll
        for (int nt = 0; nt < 8; nt++) {
            const unsigned* bp = Bsu + (k0 + lc) * BS_STRIDE + wn + nt * 8 + lr;
            b[nt][0] = bp[0];
            b[nt][1] = bp[4 * BS_STRIDE];
        }
        #pragma unroll
        for (int mt = 0; mt < 2; mt++)
            #pragma unroll
            for (int nt = 0; nt < 8; nt++)
                mma_tf32(acc[mt][nt], a[mt], b[nt]);
    }

    #pragma unroll
    for (int mt = 0; mt < 2; mt++) {
        #pragma unroll
        for (int nt = 0; nt < 8; nt++) {
            int row = m0 + wm + mt * 16 + lr;
            int col = n0 + wn + nt * 8 + lc * 2;
            float b0 = bias ? bias[col] : 0.0f;
            float b1 = bias ? bias[col + 1] : 0.0f;
            if (row < M) {
                float2 v = make_float2(acc[mt][nt][0] + b0, acc[mt][nt][1] + b1);
                *reinterpret_cast<float2*>(C + (size_t)row * Nw + col) = v;
            }
            if (row + 8 < M) {
                float2 v = make_float2(acc[mt][nt][2] + b0, acc[mt][nt][3] + b1);
                *reinterpret_cast<float2*>(C + (size_t)(row + 8) * Nw + col) = v;
            }
        }
    }
}

// ---------------- CSR aggregation: warp per node ------------------------------
// agg[n] = sum_{e in in(n)} m[src(e)] * w(e);  m = d_mgh[:, 0:128] (stride 512)
__global__ void k_agg() {
    int warp = (blockIdx.x * blockDim.x + threadIdx.x) >> 5;
    if (warp >= Nn) return;
    int lane = threadIdx.x & 31;
    int beg = d_rowstart[warp];
    int end = d_rowstart[warp + 1];
    float4 acc = make_float4(0.f, 0.f, 0.f, 0.f);
    for (int base = beg; base < end; base += 32) {
        int idx = base + lane;
        int sid = 0;
        float w = 0.0f;
        if (idx < end) { sid = d_esrc[idx]; w = d_ews[idx]; }
        int cnt = min(32, end - base);
        #pragma unroll 4
        for (int j = 0; j < cnt; j++) {
            int s = __shfl_sync(0xffffffff, sid, j);
            float wj = __shfl_sync(0xffffffff, w, j);
            float4 v = *reinterpret_cast<const float4*>(
                d_mgh + (size_t)s * 512 + lane * 4);
            acc.x = fmaf(v.x, wj, acc.x);
            acc.y = fmaf(v.y, wj, acc.y);
            acc.z = fmaf(v.z, wj, acc.z);
            acc.w = fmaf(v.w, wj, acc.w);
        }
    }
    *reinterpret_cast<float4*>(d_agg + (size_t)warp * 128 + lane * 4) = acc;
}

// ---------------- GRU --------------------------------------------------------
__global__ void k_gru() {
    int n = blockIdx.x;
    int f = threadIdx.x;
    const float* gi = d_gi + (size_t)n * 384;
    const float* gh = d_mgh + (size_t)n * 512 + 128;
    float r  = sigmoidf_(gi[f] + gh[f]);
    float z  = sigmoidf_(gi[128 + f] + gh[128 + f]);
    float nn = tanhf(gi[256 + f] + r * gh[256 + f]);
    float ho = d_h[(size_t)n * 128 + f];
    d_h[(size_t)n * 128 + f] = (1.0f - z) * nn + z * ho;
}

// ---------------- pooling + MLP ----------------------------------------------
__global__ void k_pool_init() {
    int i = blockIdx.x * blockDim.x + threadIdx.x;
    if (i < Gg * Hh) d_pooled[i] = -INFINITY;
}

__global__ void k_pool(const int* __restrict__ batch) {
    int i = blockIdx.x * blockDim.x + threadIdx.x;
    if (i >= Nn * Hh) return;
    int n = i >> 7, f = i & 127;
    float v = d_h[i];
    int g = batch[n];
    float* addr = &d_pooled[g * Hh + f];
    if (v >= 0.0f)
        atomicMax(reinterpret_cast<int*>(addr), __float_as_int(v));
    else
        atomicMin(reinterpret_cast<unsigned*>(addr), __float_as_uint(v));
}

__global__ void k_mlp1(const float* __restrict__ w, const float* __restrict__ b) {
    __shared__ float p[Hh];
    int g = blockIdx.x;
    p[threadIdx.x] = d_pooled[g * Hh + threadIdx.x];
    __syncthreads();
    for (int o = threadIdx.x; o < 4 * Hh; o += blockDim.x) {
        const float* wr = w + (size_t)o * Hh;
        float s = b[o];
        #pragma unroll 4
        for (int k = 0; k < Hh; k++) s = fmaf(p[k], wr[k], s);
        d_hid[g * 4 * Hh + o] = fmaxf(s, 0.0f);
    }
}

__global__ void k_mlp2(const float* __restrict__ w, const float* __restrict__ b,
                       float* __restrict__ out) {
    __shared__ float hsh[4 * Hh];
    int g = blockIdx.x;
    for (int i = threadIdx.x; i < 4 * Hh; i += blockDim.x)
        hsh[i] = d_hid[g * 4 * Hh + i];
    __syncthreads();
    int warp = threadIdx.x >> 5, lane = threadIdx.x & 31;
    if (warp < Cc) {
        const float* wr = w + (size_t)warp * (4 * Hh);
        float s = 0.0f;
        for (int k = lane; k < 4 * Hh; k += 32) s = fmaf(hsh[k], wr[k], s);
        #pragma unroll
        for (int off = 16; off; off >>= 1)
            s += __shfl_down_sync(0xffffffff, s, off);
        if (lane == 0) out[g * Cc + warp] = s + b[warp];
    }
}

// ---------------- launch ------------------------------------------------------
extern "C" void kernel_launch(void* const* d_in, const int* in_sizes, int n_in,
                              void* d_out, int out_size) {
    const float* x     = (const float*)d_in[0];
    const int*   ei    = (const int*)  d_in[1];
    const int*   batch = (const int*)  d_in[2];
    const float* ew    = (const float*)d_in[3];
    const float* weight= (const float*)d_in[4];
    const float* w_ih  = (const float*)d_in[5];
    const float* w_hh  = (const float*)d_in[6];
    const float* b_ih  = (const float*)d_in[7];
    const float* b_hh  = (const float*)d_in[8];
    const float* d1w   = (const float*)d_in[9];
    const float* d1b   = (const float*)d_in[10];
    const float* d2w   = (const float*)d_in[11];
    const float* d2b   = (const float*)d_in[12];
    float* out = (float*)d_out;

    float *ph, *pmgh, *pagg, *pgi, *pwihT, *pBcat, *pbcat;
    cudaGetSymbolAddress((void**)&ph,    d_h);
    cudaGetSymbolAddress((void**)&pmgh,  d_mgh);
    cudaGetSymbolAddress((void**)&pagg,  d_agg);
    cudaGetSymbolAddress((void**)&pgi,   d_gi);
    cudaGetSymbolAddress((void**)&pwihT, d_wihT);
    cudaGetSymbolAddress((void**)&pBcat, d_Bcat);
    cudaGetSymbolAddress((void**)&pbcat, d_bcat);

    const int GEMM_SMEM = (128 * AS_STRIDE + 128 * BS_STRIDE) * (int)sizeof(float);
    cudaFuncSetAttribute(k_gemm_tc, cudaFuncAttributeMaxDynamicSharedMemorySize,
                         GEMM_SMEM);

    const int NH = Nn * Hh;
    // setup
    k_init_h<<<(NH + 255) / 256, 256>>>(x);
    k_transpose_wih<<<(3 * Hh * Hh + 255) / 256, 256>>>(w_ih);
    k_build_bcat<<<(Ll * Hh * 512 + 255) / 256, 256>>>(weight, w_hh, b_hh);
    // CSR build
    k_deg_zero<<<(Nn + 255) / 256, 256>>>();
    k_hist<<<(Ee + 255) / 256, 256>>>(ei);
    k_scan<<<1, 1024>>>();
    k_scatter<<<(Ee + 255) / 256, 256>>>(ei, ew);

    const int MB = (Nn + 127) / 128;  // 391 row tiles
    for (int l = 0; l < Ll; l++) {
        // [m | gh] = h @ [W_l | w_hh^T]   (bias [0 | b_hh])
        k_gemm_tc<<<dim3(MB, 4), 256, GEMM_SMEM>>>(
            ph, pBcat + (size_t)l * Hh * 512, pbcat, pmgh, Nn, 512);
        // agg = CSR gather of m[src]*w
        k_agg<<<(Nn * 32 + 255) / 256, 256>>>();
        // gi = agg @ w_ih^T + b_ih
        k_gemm_tc<<<dim3(MB, 3), 256, GEMM_SMEM>>>(pagg, pwihT, b_ih, pgi, Nn, 3 * Hh);
        // h = GRU(agg, h)
        k_gru<<<Nn, Hh>>>();
    }

    k_pool_init<<<(Gg * Hh + 255) / 256, 256>>>();
    k_pool<<<(NH + 255) / 256, 256>>>(batch);
    k_mlp1<<<Gg, Hh>>>(d1w, d1b);
    k_mlp2<<<Gg, 320>>>(d2w, d2b, out);
}